// round 14
// baseline (speedup 1.0000x reference)
#include <cuda_runtime.h>
#include <stdint.h>

// ROISelect: per-row top-k(score) + ROI gather.
// Kernel 1 (hot, fused): grid (2,128). Each CTA scans half a row
//   (16 float4/thread, 2 CTAs/SM => 64 warps/SM), filters score >= 2.80
//   (~168 cand/half) into a 16KB smem stage, flushes to global scratch with
//   one atomic. The LAST CTA per row becomes the finisher: if the row's
//   candidate count is in [256, 512] (mean 335, sigma 18 => 9.8-sigma safe),
//   it computes exact sorted ranks (2 threads/candidate, unique u64 keys
//   value|~index matching tf.nn.top_k tie order) and emits out[rank] + ROI
//   gather, overlapping other rows' scans. Otherwise it sets g_flag[row].
// Kernel 2 (cleanup, normally no-op): per row, if flagged, exact 12-bit
//   radix-select over the raw row + serial rank + emit. Guarantees
//   correctness for ANY input; cold code lives here so the hot kernel's
//   register allocation stays scan-optimal (R13 lesson: fallback bloat in
//   the hot kernel made ptxas pick 32 regs and halved scan throughput).

#define B_ROWS 128
#define N_COLS 131072
#define K_TOP  256
#define CAP    4096
#define FASTC  512                            // fast-path max candidate count

#define TPB        1024
#define HALVES     2
#define HALF_ELEMS (N_COLS / HALVES)          // 65536
#define A_V4       (HALF_ELEMS / 4 / TPB)     // 16 float4 per thread
#define A_GROUPS   4
#define A_GSIZE    (A_V4 / A_GROUPS)          // 4 float4 per load group
#define SCAP       2048                       // smem stage per CTA (16 KB)
#define VEC_ITERS  (N_COLS / 4 / TPB)         // 32 (cleanup only)

__device__ unsigned long long g_cand[B_ROWS * CAP];
__device__ unsigned int       g_cnt[B_ROWS];    // zero at load; finisher resets
__device__ unsigned int       g_done[B_ROWS];   // zero at load; finisher resets
__device__ unsigned int       g_flag[B_ROWS];   // zero at load; cleanup resets

__device__ __forceinline__ unsigned int f2u(float f) {
    unsigned int b = __float_as_uint(f);
    return (b & 0x80000000u) ? ~b : (b | 0x80000000u);
}
__device__ __forceinline__ float u2f(unsigned int u) {
    unsigned int b = (u & 0x80000000u) ? (u ^ 0x80000000u) : ~u;
    return __uint_as_float(b);
}

// ================= Kernel 1: fused scan + fast finisher =================
__global__ __launch_bounds__(TPB, 2)
void roisel_scan_finish_kernel(const float* __restrict__ score,
                               const float* __restrict__ roi,
                               float* __restrict__ out_roi,
                               float* __restrict__ out_score)
{
    __shared__ unsigned long long stage[SCAP];       // 16 KB
    __shared__ unsigned long long cand[FASTC + 1];   // ~4 KB (fast finisher)
    __shared__ unsigned int s_half[TPB];             // 4 KB split-rank partials
    __shared__ int s_cnt;
    __shared__ unsigned int s_base;
    __shared__ unsigned int s_fin;
    __shared__ unsigned int s_count;

    const int tid  = threadIdx.x;
    const int half = blockIdx.x;
    const int row  = blockIdx.y;

    if (tid == 0) s_cnt = 0;
    __syncthreads();

    // ---------- Scan: filter half a row into the smem stage ----------
    const float4* sc4 =
        (const float4*)(score + (size_t)row * N_COLS + (size_t)half * HALF_ELEMS);
    const int gbase = half * HALF_ELEMS;
    const float TGUESS = 2.80f;

    #pragma unroll
    for (int g = 0; g < A_GROUPS; ++g) {
        float4 v[A_GSIZE];
        #pragma unroll
        for (int u = 0; u < A_GSIZE; ++u)
            v[u] = sc4[tid + (g * A_GSIZE + u) * TPB];
        #pragma unroll
        for (int u = 0; u < A_GSIZE; ++u) {
            int ebase = gbase + (tid + (g * A_GSIZE + u) * TPB) * 4;
            float vals[4] = {v[u].x, v[u].y, v[u].z, v[u].w};
            #pragma unroll
            for (int c = 0; c < 4; ++c) {
                if (vals[c] >= TGUESS) {
                    int pos = atomicAdd(&s_cnt, 1);
                    if (pos < SCAP) {
                        unsigned int uu = __float_as_uint(vals[c]) | 0x80000000u;
                        stage[pos] = ((unsigned long long)uu << 32)
                                   | (unsigned int)~(unsigned int)(ebase + c);
                    }
                }
            }
        }
    }
    __syncthreads();

    // ---------- Flush stage -> global scratch ----------
    {
        int raw = s_cnt;
        int cnt = min(raw, SCAP);
        if (tid == 0) {
            unsigned int add = (unsigned int)raw;
            if (raw > SCAP) add += (1u << 20);   // overflow marker -> cleanup
            s_base = atomicAdd(&g_cnt[row], add);
        }
        __syncthreads();
        unsigned int base = s_base;
        unsigned long long* dst = g_cand + (size_t)row * CAP;
        for (int i = tid; i < cnt; i += TPB) {
            unsigned int p = base + (unsigned int)i;
            if (p < CAP) dst[p] = stage[i];
        }
    }

    // ---------- Last-CTA-per-row election ----------
    // __syncthreads() makes every thread's prior global writes happen-before
    // thread 0's fence; the fence + atomic publish them (release), and the
    // finisher's fence after observing the count acquires the peer's writes.
    __syncthreads();
    if (tid == 0) {
        __threadfence();
        unsigned int old = atomicAdd(&g_done[row], 1u);
        unsigned int fin = (old == HALVES - 1) ? 1u : 0u;
        if (fin) {
            __threadfence();
            s_count = g_cnt[row];
            g_cnt[row]  = 0;                    // reset for next graph replay
            g_done[row] = 0;
        }
        s_fin = fin;
    }
    __syncthreads();
    if (!s_fin) return;

    unsigned int count = s_count;
    if (count < K_TOP || count > FASTC) {       // includes overflow markers
        if (tid == 0) g_flag[row] = 1u;         // defer to cleanup kernel
        return;
    }

    // ---------- Fast finisher: load candidates ----------
    const unsigned long long* src = g_cand + (size_t)row * CAP;
    if (tid < (int)count) cand[tid] = src[tid];            // count <= 512
    if (tid == 0 && (count & 1u)) cand[count] = 0ULL;      // even pad (bit63=0)
    __syncthreads();

    const int pairs = (int)((count + 1u) >> 1);
    const ulonglong2* c2 = (const ulonglong2*)cand;

    // ---------- Split rank: 2 threads per candidate ----------
    const int t     = tid & 511;
    const int which = tid >> 9;
    const int ph    = pairs >> 1;
    const int i0    = which ? ph : 0;
    const int i1    = which ? pairs : ph;
    unsigned int partial = 0;
    if (t < (int)count) {
        const unsigned long long key = cand[t];
        #pragma unroll 4
        for (int i = i0; i < i1; ++i) {
            ulonglong2 p = c2[i];
            partial += (p.x > key) + (p.y > key);
        }
    }
    s_half[tid] = partial;
    __syncthreads();

    if (tid < (int)count) {
        unsigned int rank = s_half[tid] + s_half[tid + 512];
        if (rank < K_TOP) {
            unsigned long long key = cand[tid];
            unsigned int u   = (unsigned int)(key >> 32);
            unsigned int idx = ~(unsigned int)key;
            const float4* r4 = (const float4*)roi;
            float4 rv = r4[(size_t)row * N_COLS + idx];
            out_score[row * K_TOP + tid - tid + rank] = u2f(u);
            ((float4*)out_roi)[row * K_TOP + rank] = rv;
        }
    }
}

// ================= Kernel 2: cleanup (normally a no-op) =================
__global__ __launch_bounds__(TPB, 1)
void roisel_cleanup_kernel(const float* __restrict__ score,
                           const float* __restrict__ roi,
                           float* __restrict__ out_roi,
                           float* __restrict__ out_score)
{
    __shared__ unsigned int s_flag;
    __shared__ int s_cnt;
    __shared__ int s_bin;
    extern __shared__ unsigned long long cand[];   // CAP entries = 32 KB

    const int tid = threadIdx.x;
    const int row = blockIdx.x;

    if (tid == 0) s_flag = g_flag[row];
    __syncthreads();
    if (!s_flag) return;                           // fast exit: nothing to fix
    if (tid == 0) { g_flag[row] = 0u; s_cnt = 0; } // reset for next replay
    __syncthreads();

    // ---------- Exact 12-bit radix select over the raw row ----------
    const float4* sc4 = (const float4*)(score + (size_t)row * N_COLS);
    unsigned int* hist  = (unsigned int*)cand;     // 4096 bins (aliased)
    unsigned int* sdata = hist + 4096;             // 1024 thread sums
    for (int i = tid; i < 4096; i += TPB) hist[i] = 0;
    __syncthreads();

    for (int i = 0; i < VEC_ITERS; ++i) {
        float4 f = sc4[tid + i * TPB];
        float vals[4] = {f.x, f.y, f.z, f.w};
        #pragma unroll
        for (int c = 0; c < 4; ++c)
            atomicAdd(&hist[f2u(vals[c]) >> 20], 1u);
    }
    __syncthreads();

    unsigned int h0 = hist[4*tid+0], h1 = hist[4*tid+1];
    unsigned int h2 = hist[4*tid+2], h3 = hist[4*tid+3];
    sdata[tid] = h0 + h1 + h2 + h3;
    __syncthreads();
    for (int d = 1; d < TPB; d <<= 1) {            // inclusive suffix scan
        unsigned int vv = (tid + d < TPB) ? sdata[tid + d] : 0u;
        __syncthreads();
        sdata[tid] += vv;
        __syncthreads();
    }
    unsigned int Anext = (tid + 1 < TPB) ? sdata[tid + 1] : 0u;
    unsigned int cum3 = Anext + h3;
    unsigned int cum2 = cum3 + h2;
    unsigned int cum1 = cum2 + h1;
    unsigned int cum0 = cum1 + h0;
    if (cum3 >= K_TOP && Anext < K_TOP) s_bin = 4*tid + 3;
    if (cum2 >= K_TOP && cum3  < K_TOP) s_bin = 4*tid + 2;
    if (cum1 >= K_TOP && cum2  < K_TOP) s_bin = 4*tid + 1;
    if (cum0 >= K_TOP && cum1  < K_TOP) s_bin = 4*tid + 0;
    __syncthreads();
    unsigned int uthr = (unsigned int)s_bin << 20;
    __syncthreads();   // uthr read by all; hist region can be overwritten

    for (int i = 0; i < VEC_ITERS; ++i) {
        int v4i = tid + i * TPB;
        float4 f = sc4[v4i];
        int ebase = v4i * 4;
        float vals[4] = {f.x, f.y, f.z, f.w};
        #pragma unroll
        for (int c = 0; c < 4; ++c) {
            unsigned int u = f2u(vals[c]);
            if (u >= uthr) {
                int pos = atomicAdd(&s_cnt, 1);
                if (pos < CAP)
                    cand[pos] = ((unsigned long long)u << 32)
                              | (unsigned int)~(unsigned int)(ebase + c);
            }
        }
    }
    __syncthreads();
    unsigned int count = min((unsigned int)s_cnt, (unsigned int)CAP);

    if (tid == 0 && (count & 1u)) cand[count] = 0ULL;   // even pad
    __syncthreads();
    const int pairs = (int)((count + 1u) >> 1);
    const ulonglong2* c2 = (const ulonglong2*)cand;

    // ---------- Serial rank + emit (rare path; exactness over speed) ----------
    for (int c = tid; c < (int)count; c += TPB) {
        unsigned long long key = cand[c];
        int rank = 0;
        #pragma unroll 8
        for (int i = 0; i < pairs; ++i) {
            ulonglong2 p = c2[i];
            rank += (p.x > key) + (p.y > key);
        }
        if (rank < K_TOP) {
            unsigned int u   = (unsigned int)(key >> 32);
            unsigned int idx = ~(unsigned int)key;
            const float4* r4 = (const float4*)roi;
            float4 rv = r4[(size_t)row * N_COLS + idx];
            out_score[row * K_TOP + rank] = u2f(u);
            ((float4*)out_roi)[row * K_TOP + rank] = rv;
        }
    }
}

extern "C" void kernel_launch(void* const* d_in, const int* in_sizes, int n_in,
                              void* d_out, int out_size) {
    (void)in_sizes; (void)n_in; (void)out_size;
    const float* score = (const float*)d_in[0];
    const float* roi   = (const float*)d_in[1];
    float* out_roi   = (float*)d_out;                               // [128,256,4]
    float* out_score = (float*)d_out + (size_t)B_ROWS * K_TOP * 4;  // [128,256]

    dim3 grid(HALVES, B_ROWS);
    roisel_scan_finish_kernel<<<grid, TPB>>>(score, roi, out_roi, out_score);
    roisel_cleanup_kernel<<<B_ROWS, TPB, CAP * sizeof(unsigned long long)>>>(
        score, roi, out_roi, out_score);
}

// round 15
// speedup vs baseline: 1.1000x; 1.1000x over previous
#include <cuda_runtime.h>
#include <stdint.h>

// ROISelect: per-row top-k(score) + ROI gather, SINGLE fused kernel.
// Grid (2,128), TPB=1024, 2 CTAs/SM. Each CTA scans half a row (16 float4/
// thread), filters score >= 2.80 into a 16KB smem stage, flushes to global
// scratch with one atomic. The LAST CTA per row (arrival counter + fences)
// becomes the finisher. Finisher + exact fallback are __noinline__ device
// functions so their register pressure cannot degrade the scan loop's
// allocation (R13/R14 lesson: inlined cold code made ptxas pick 32 regs and
// halved scan throughput). Fast path: count in [256,512] -> split-rank
// (2 threads/candidate, unique u64 keys value|~index, tf.nn.top_k tie
// order). Any other count -> exact 12-bit radix-select over the raw row.
// No second kernel: measured per-kernel graph overhead is ~4.5us.
//
// SMEM: one 32KB dynamic arena, phase-disjoint overlays:
//   scan:     stage[2048]  u64   16KB   (dead after flush)
//   fast fin: cand[520] u64 ~4KB | s_half[1024] u32 4KB
//   fallback: hist[4096] u32 16KB + sdata[1024] u32 4KB, then cand[4096] u64 32KB

#define B_ROWS 128
#define N_COLS 131072
#define K_TOP  256
#define CAP    4096
#define FASTC  512

#define TPB        1024
#define HALVES     2
#define HALF_ELEMS (N_COLS / HALVES)          // 65536
#define A_V4       (HALF_ELEMS / 4 / TPB)     // 16 float4 per thread
#define A_GROUPS   4
#define A_GSIZE    (A_V4 / A_GROUPS)          // 4 float4 per load group
#define SCAP       2048                       // smem stage (16 KB)
#define VEC_ITERS  (N_COLS / 4 / TPB)         // 32 (fallback only)

#define ARENA_BYTES (CAP * 8)                 // 32 KB dynamic

__device__ unsigned long long g_cand[B_ROWS * CAP];
__device__ unsigned int       g_cnt[B_ROWS];    // zero at load; finisher resets
__device__ unsigned int       g_done[B_ROWS];   // zero at load; finisher resets

__device__ __forceinline__ unsigned int f2u(float f) {
    unsigned int b = __float_as_uint(f);
    return (b & 0x80000000u) ? ~b : (b | 0x80000000u);
}
__device__ __forceinline__ float u2f(unsigned int u) {
    unsigned int b = (u & 0x80000000u) ? (u ^ 0x80000000u) : ~u;
    return __uint_as_float(b);
}

// ---------------- Cold: fast finisher (count in [K_TOP, FASTC]) ----------------
__device__ __noinline__
void fast_finish(unsigned long long* arena, int row, unsigned int count,
                 const float* roi, float* out_roi, float* out_score)
{
    unsigned long long* cand   = arena;                          // 520 u64
    unsigned int*       s_half = (unsigned int*)(arena + 520);   // 1024 u32
    const int tid = threadIdx.x;

    const unsigned long long* src = g_cand + (size_t)row * CAP;
    if (tid < (int)count) cand[tid] = src[tid];               // count <= 512
    if (tid == 0 && (count & 1u)) cand[count] = 0ULL;         // even pad, bit63=0
    __syncthreads();

    const int pairs = (int)((count + 1u) >> 1);
    const ulonglong2* c2 = (const ulonglong2*)cand;

    const int t     = tid & 511;
    const int which = tid >> 9;
    const int ph    = pairs >> 1;
    const int i0    = which ? ph : 0;
    const int i1    = which ? pairs : ph;
    unsigned int partial = 0;
    if (t < (int)count) {
        const unsigned long long key = cand[t];
        #pragma unroll 4
        for (int i = i0; i < i1; ++i) {
            ulonglong2 p = c2[i];
            partial += (p.x > key) + (p.y > key);
        }
    }
    s_half[tid] = partial;
    __syncthreads();

    if (tid < (int)count) {
        unsigned int rank = s_half[tid] + s_half[tid + 512];
        if (rank < K_TOP) {
            unsigned long long key = cand[tid];
            unsigned int u   = (unsigned int)(key >> 32);
            unsigned int idx = ~(unsigned int)key;
            const float4* r4 = (const float4*)roi;
            float4 rv = r4[(size_t)row * N_COLS + idx];
            out_score[row * K_TOP + rank] = u2f(u);
            ((float4*)out_roi)[row * K_TOP + rank] = rv;
        }
    }
}

// ---------------- Cold: exact fallback (any count) ----------------
__device__ __noinline__
void fallback_finish(unsigned long long* arena, int row,
                     const float* score, const float* roi,
                     float* out_roi, float* out_score)
{
    __shared__ int fb_cnt;
    __shared__ int fb_bin;
    const int tid = threadIdx.x;

    unsigned long long* cand  = arena;                       // 4096 u64 (phase 2)
    unsigned int*       hist  = (unsigned int*)arena;        // 4096 u32 (phase 1)
    unsigned int*       sdata = hist + 4096;                 // 1024 u32

    const float4* sc4 = (const float4*)(score + (size_t)row * N_COLS);
    for (int i = tid; i < 4096; i += TPB) hist[i] = 0;
    if (tid == 0) fb_cnt = 0;
    __syncthreads();

    for (int i = 0; i < VEC_ITERS; ++i) {
        float4 f = sc4[tid + i * TPB];
        float vals[4] = {f.x, f.y, f.z, f.w};
        #pragma unroll
        for (int c = 0; c < 4; ++c)
            atomicAdd(&hist[f2u(vals[c]) >> 20], 1u);
    }
    __syncthreads();

    unsigned int h0 = hist[4*tid+0], h1 = hist[4*tid+1];
    unsigned int h2 = hist[4*tid+2], h3 = hist[4*tid+3];
    sdata[tid] = h0 + h1 + h2 + h3;
    __syncthreads();
    for (int d = 1; d < TPB; d <<= 1) {            // inclusive suffix scan
        unsigned int vv = (tid + d < TPB) ? sdata[tid + d] : 0u;
        __syncthreads();
        sdata[tid] += vv;
        __syncthreads();
    }
    unsigned int Anext = (tid + 1 < TPB) ? sdata[tid + 1] : 0u;
    unsigned int cum3 = Anext + h3;
    unsigned int cum2 = cum3 + h2;
    unsigned int cum1 = cum2 + h1;
    unsigned int cum0 = cum1 + h0;
    if (cum3 >= K_TOP && Anext < K_TOP) fb_bin = 4*tid + 3;
    if (cum2 >= K_TOP && cum3  < K_TOP) fb_bin = 4*tid + 2;
    if (cum1 >= K_TOP && cum2  < K_TOP) fb_bin = 4*tid + 1;
    if (cum0 >= K_TOP && cum1  < K_TOP) fb_bin = 4*tid + 0;
    __syncthreads();
    unsigned int uthr = (unsigned int)fb_bin << 20;
    __syncthreads();     // uthr read; hist/sdata region may be overwritten

    for (int i = 0; i < VEC_ITERS; ++i) {
        int v4i = tid + i * TPB;
        float4 f = sc4[v4i];
        int ebase = v4i * 4;
        float vals[4] = {f.x, f.y, f.z, f.w};
        #pragma unroll
        for (int c = 0; c < 4; ++c) {
            unsigned int u = f2u(vals[c]);
            if (u >= uthr) {
                int pos = atomicAdd(&fb_cnt, 1);
                if (pos < CAP)
                    cand[pos] = ((unsigned long long)u << 32)
                              | (unsigned int)~(unsigned int)(ebase + c);
            }
        }
    }
    __syncthreads();
    unsigned int count = min((unsigned int)fb_cnt, (unsigned int)CAP);

    if (tid == 0 && (count & 1u)) cand[count] = 0ULL;
    __syncthreads();
    const int pairs = (int)((count + 1u) >> 1);
    const ulonglong2* c2 = (const ulonglong2*)cand;

    for (int c = tid; c < (int)count; c += TPB) {
        unsigned long long key = cand[c];
        int rank = 0;
        #pragma unroll 8
        for (int i = 0; i < pairs; ++i) {
            ulonglong2 p = c2[i];
            rank += (p.x > key) + (p.y > key);
        }
        if (rank < K_TOP) {
            unsigned int u   = (unsigned int)(key >> 32);
            unsigned int idx = ~(unsigned int)key;
            const float4* r4 = (const float4*)roi;
            float4 rv = r4[(size_t)row * N_COLS + idx];
            out_score[row * K_TOP + rank] = u2f(u);
            ((float4*)out_roi)[row * K_TOP + rank] = rv;
        }
    }
}

// ---------------- Hot: fused scan + finisher dispatch ----------------
__global__ __launch_bounds__(TPB, 2)
void roiselect_fused_kernel(const float* __restrict__ score,
                            const float* __restrict__ roi,
                            float* __restrict__ out_roi,
                            float* __restrict__ out_score)
{
    __shared__ int s_cnt;
    __shared__ unsigned int s_base;
    __shared__ unsigned int s_fin;
    __shared__ unsigned int s_count;
    extern __shared__ unsigned long long arena[];   // 32 KB
    unsigned long long* stage = arena;              // first 16 KB during scan

    const int tid  = threadIdx.x;
    const int half = blockIdx.x;
    const int row  = blockIdx.y;

    if (tid == 0) s_cnt = 0;
    __syncthreads();

    // ---------- Scan: filter half a row into the smem stage ----------
    const float4* sc4 =
        (const float4*)(score + (size_t)row * N_COLS + (size_t)half * HALF_ELEMS);
    const int gbase = half * HALF_ELEMS;
    const float TGUESS = 2.80f;

    #pragma unroll
    for (int g = 0; g < A_GROUPS; ++g) {
        float4 v[A_GSIZE];
        #pragma unroll
        for (int u = 0; u < A_GSIZE; ++u)
            v[u] = sc4[tid + (g * A_GSIZE + u) * TPB];
        #pragma unroll
        for (int u = 0; u < A_GSIZE; ++u) {
            int ebase = gbase + (tid + (g * A_GSIZE + u) * TPB) * 4;
            float vals[4] = {v[u].x, v[u].y, v[u].z, v[u].w};
            #pragma unroll
            for (int c = 0; c < 4; ++c) {
                if (vals[c] >= TGUESS) {
                    int pos = atomicAdd(&s_cnt, 1);
                    if (pos < SCAP) {
                        unsigned int uu = __float_as_uint(vals[c]) | 0x80000000u;
                        stage[pos] = ((unsigned long long)uu << 32)
                                   | (unsigned int)~(unsigned int)(ebase + c);
                    }
                }
            }
        }
    }
    __syncthreads();

    // ---------- Flush stage -> global scratch ----------
    {
        int raw = s_cnt;
        int cnt = min(raw, SCAP);
        if (tid == 0) {
            unsigned int add = (unsigned int)raw;
            if (raw > SCAP) add += (1u << 20);   // overflow marker -> fallback
            s_base = atomicAdd(&g_cnt[row], add);
        }
        __syncthreads();
        unsigned int base = s_base;
        unsigned long long* dst = g_cand + (size_t)row * CAP;
        for (int i = tid; i < cnt; i += TPB) {
            unsigned int p = base + (unsigned int)i;
            if (p < CAP) dst[p] = stage[i];
        }
    }

    // ---------- Last-CTA-per-row election (release/acquire via fences) ----------
    __threadfence();                 // every thread publishes its g_cand writes
    __syncthreads();
    if (tid == 0) {
        unsigned int old = atomicAdd(&g_done[row], 1u);
        unsigned int fin = (old == HALVES - 1) ? 1u : 0u;
        if (fin) {
            __threadfence();         // acquire: see peer CTA's g_cand writes
            s_count = g_cnt[row];
            g_cnt[row]  = 0;         // reset for next graph replay
            g_done[row] = 0;
        }
        s_fin = fin;
    }
    __syncthreads();
    if (!s_fin) return;

    unsigned int count = s_count;
    if (count >= K_TOP && count <= FASTC)
        fast_finish(arena, row, count, roi, out_roi, out_score);
    else
        fallback_finish(arena, row, score, roi, out_roi, out_score);
}

extern "C" void kernel_launch(void* const* d_in, const int* in_sizes, int n_in,
                              void* d_out, int out_size) {
    (void)in_sizes; (void)n_in; (void)out_size;
    const float* score = (const float*)d_in[0];
    const float* roi   = (const float*)d_in[1];
    float* out_roi   = (float*)d_out;                               // [128,256,4]
    float* out_score = (float*)d_out + (size_t)B_ROWS * K_TOP * 4;  // [128,256]

    dim3 grid(HALVES, B_ROWS);
    roiselect_fused_kernel<<<grid, TPB, ARENA_BYTES>>>(
        score, roi, out_roi, out_score);
}

// round 16
// speedup vs baseline: 1.4776x; 1.3433x over previous
#include <cuda_runtime.h>
#include <stdint.h>

// ROISelect: per-row top-k(score) + ROI gather, monolithic, sort-free.
// One CTA (1024 thr) per row: float4 streaming scan with 8 front-batched
// LDG.128 per load group (MLP_eff ~8; the R5/R10 4-load groups measured
// MLP_eff ~2 => 3.3 TB/s scan) filters score >= 2.80 (~335 cand/row,
// 4.3-sigma margin) into shared memory, then exact sorted ranks via split
// all-pairs comparison (2 threads per candidate, unique u64 keys
// value|~index matching tf.nn.top_k tie order), writing out[rank] directly.
// Exact 12-bit radix-select fallback if count is outside [256, 4096].

#define B_ROWS 128
#define N_COLS 131072
#define K_TOP  256
#define TPB    1024
#define CAP    4096
#define V4_PER_THREAD (N_COLS / 4 / TPB)   // 32
#define GROUPS 4
#define GSIZE  (V4_PER_THREAD / GROUPS)    // 8 float4 per load group

__device__ __forceinline__ unsigned int f2u(float f) {
    unsigned int b = __float_as_uint(f);
    return (b & 0x80000000u) ? ~b : (b | 0x80000000u);
}
__device__ __forceinline__ float u2f(unsigned int u) {
    unsigned int b = (u & 0x80000000u) ? (u ^ 0x80000000u) : ~u;
    return __uint_as_float(b);
}

__global__ __launch_bounds__(TPB, 1)
void roiselect_kernel(const float* __restrict__ score,
                      const float* __restrict__ roi,
                      float* __restrict__ out_roi,
                      float* __restrict__ out_score)
{
    __shared__ int s_cnt;
    __shared__ int s_bin;
    __shared__ unsigned int s_half[TPB];           // split-rank partials (4 KB)
    extern __shared__ unsigned long long cand[];   // CAP entries = 32 KB

    const int tid = threadIdx.x;
    const int row = blockIdx.x;
    const float4* sc4 = (const float4*)(score + (size_t)row * N_COLS);

    if (tid == 0) s_cnt = 0;
    __syncthreads();

    // ---------- Streaming filter: groups of 8 front-batched LDG.128 ----------
    const float TGUESS = 2.80f;
    #pragma unroll
    for (int g = 0; g < GROUPS; ++g) {
        float4 v[GSIZE];
        #pragma unroll
        for (int u = 0; u < GSIZE; ++u)
            v[u] = sc4[tid + (g * GSIZE + u) * TPB];
        #pragma unroll
        for (int u = 0; u < GSIZE; ++u) {
            int ebase = (tid + (g * GSIZE + u) * TPB) * 4;
            float vals[4] = {v[u].x, v[u].y, v[u].z, v[u].w};
            #pragma unroll
            for (int c = 0; c < 4; ++c) {
                if (vals[c] >= TGUESS) {
                    int pos = atomicAdd(&s_cnt, 1);
                    if (pos < CAP) {
                        unsigned int uu = __float_as_uint(vals[c]) | 0x80000000u;
                        cand[pos] = ((unsigned long long)uu << 32)
                                  | (unsigned int)~(unsigned int)(ebase + c);
                    }
                }
            }
        }
    }
    __syncthreads();
    unsigned int count = (unsigned int)s_cnt;

    // ---------- Exact fallback: 12-bit radix select (never taken on this data) ----------
    if (count < K_TOP || count > CAP) {
        unsigned int* hist  = (unsigned int*)cand;   // 4096 bins (aliased)
        unsigned int* sdata = hist + 4096;           // 1024 thread sums
        for (int i = tid; i < 4096; i += TPB) hist[i] = 0;
        if (tid == 0) s_cnt = 0;
        __syncthreads();

        for (int i = 0; i < V4_PER_THREAD; ++i) {
            float4 f = sc4[tid + i * TPB];
            float vals[4] = {f.x, f.y, f.z, f.w};
            #pragma unroll
            for (int c = 0; c < 4; ++c)
                atomicAdd(&hist[f2u(vals[c]) >> 20], 1u);
        }
        __syncthreads();

        unsigned int h0 = hist[4*tid+0], h1 = hist[4*tid+1];
        unsigned int h2 = hist[4*tid+2], h3 = hist[4*tid+3];
        sdata[tid] = h0 + h1 + h2 + h3;
        __syncthreads();
        for (int d = 1; d < TPB; d <<= 1) {          // inclusive suffix scan
            unsigned int vv = (tid + d < TPB) ? sdata[tid + d] : 0u;
            __syncthreads();
            sdata[tid] += vv;
            __syncthreads();
        }
        unsigned int Anext = (tid + 1 < TPB) ? sdata[tid + 1] : 0u;
        unsigned int cum3 = Anext + h3;
        unsigned int cum2 = cum3 + h2;
        unsigned int cum1 = cum2 + h1;
        unsigned int cum0 = cum1 + h0;
        if (cum3 >= K_TOP && Anext < K_TOP) s_bin = 4*tid + 3;
        if (cum2 >= K_TOP && cum3  < K_TOP) s_bin = 4*tid + 2;
        if (cum1 >= K_TOP && cum2  < K_TOP) s_bin = 4*tid + 1;
        if (cum0 >= K_TOP && cum1  < K_TOP) s_bin = 4*tid + 0;
        __syncthreads();
        unsigned int uthr = (unsigned int)s_bin << 20;
        __syncthreads();   // uthr read by all; hist region can be overwritten

        for (int i = 0; i < V4_PER_THREAD; ++i) {
            int v4i = tid + i * TPB;
            float4 f = sc4[v4i];
            int ebase = v4i * 4;
            float vals[4] = {f.x, f.y, f.z, f.w};
            #pragma unroll
            for (int c = 0; c < 4; ++c) {
                unsigned int u = f2u(vals[c]);
                if (u >= uthr) {
                    int pos = atomicAdd(&s_cnt, 1);
                    if (pos < CAP)
                        cand[pos] = ((unsigned long long)u << 32)
                                  | (unsigned int)~(unsigned int)(ebase + c);
                }
            }
        }
        __syncthreads();
        count = min((unsigned int)s_cnt, (unsigned int)CAP);
    }

    // Pad to even for the ulonglong2 loops (a 0 key never outranks a real
    // key: all real keys have bit 63 set). count==CAP is even, so the pad
    // write never exceeds the buffer.
    if (tid == 0 && (count & 1u)) cand[count] = 0ULL;
    __syncthreads();
    const int pairs = (int)((count + 1u) >> 1);
    const ulonglong2* c2 = (const ulonglong2*)cand;

    if (count <= 512) {
        // ---------- Split rank: 2 threads per candidate ----------
        const int t     = tid & 511;            // candidate id
        const int which = tid >> 9;             // 0 = low half, 1 = high half
        const int ph    = pairs >> 1;
        const int i0    = which ? ph : 0;
        const int i1    = which ? pairs : ph;
        unsigned int partial = 0;
        if (t < (int)count) {
            const unsigned long long key = cand[t];
            #pragma unroll 4
            for (int i = i0; i < i1; ++i) {
                ulonglong2 p = c2[i];
                partial += (p.x > key) + (p.y > key);
            }
        }
        s_half[tid] = partial;
        __syncthreads();

        if (tid < (int)count) {
            unsigned int rank = s_half[tid] + s_half[tid + 512];
            if (rank < K_TOP) {
                unsigned long long key = cand[tid];
                unsigned int u   = (unsigned int)(key >> 32);
                unsigned int idx = ~(unsigned int)key;
                const float4* r4 = (const float4*)roi;
                float4 rv = r4[(size_t)row * N_COLS + idx];
                out_score[row * K_TOP + rank] = u2f(u);
                ((float4*)out_roi)[row * K_TOP + rank] = rv;
            }
        }
    } else {
        // ---------- Serial rank (fallback-sized candidate sets only) ----------
        for (int c = tid; c < (int)count; c += TPB) {
            unsigned long long key = cand[c];
            int rank = 0;
            #pragma unroll 8
            for (int i = 0; i < pairs; ++i) {
                ulonglong2 p = c2[i];
                rank += (p.x > key) + (p.y > key);
            }
            if (rank < K_TOP) {
                unsigned int u   = (unsigned int)(key >> 32);
                unsigned int idx = ~(unsigned int)key;
                const float4* r4 = (const float4*)roi;
                float4 rv = r4[(size_t)row * N_COLS + idx];
                out_score[row * K_TOP + rank] = u2f(u);
                ((float4*)out_roi)[row * K_TOP + rank] = rv;
            }
        }
    }
}

extern "C" void kernel_launch(void* const* d_in, const int* in_sizes, int n_in,
                              void* d_out, int out_size) {
    (void)in_sizes; (void)n_in; (void)out_size;
    const float* score = (const float*)d_in[0];
    const float* roi   = (const float*)d_in[1];
    float* out_roi   = (float*)d_out;                               // [128,256,4]
    float* out_score = (float*)d_out + (size_t)B_ROWS * K_TOP * 4;  // [128,256]
    roiselect_kernel<<<B_ROWS, TPB, CAP * sizeof(unsigned long long)>>>(
        score, roi, out_roi, out_score);
}